// round 15
// baseline (speedup 1.0000x reference)
#include <cuda_runtime.h>
#include <cuda_fp16.h>
#include <stdint.h>
#include <math.h>

#define NN   50000
#define EE   1600000
#define IND  256
#define HIDD 64
#define NH1  2
#define F1   128        // NH1*HIDD
#define NCLS 10
#define NEG  0.2f
#define BKT  96         // bucket capacity per node (mean deg 33, 11-sigma headroom)

// ---------------- scratch (static device globals; no allocation) ------------
__device__ __half g_x1h[NN * IND];      // fp16 copy of input x
__device__ __half g_h1[NN * F1];        // fp16 message features (layer 1)
__device__ __half g_h2[NN * HIDD];      // fp16 message features (layer 2)
__device__ float g_as1[NN * NH1], g_ad1[NN * NH1];
__device__ __half g_x2[NN * F1];        // fp16 input to GEMM2
__device__ float g_as2[NN], g_ad2[NN];

// bucketed CSR (built once per call; shared by both layers)
__device__ int g_cnt[NN];
__device__ int g_csrc[(size_t)NN * BKT];

// ---------------- helpers ----------------------------------------------------
__device__ __forceinline__ float lrelu(float x) { return x > 0.f ? x : NEG * x; }
__device__ __forceinline__ float eluf(float x)  { return x > 0.f ? x : (__expf(x) - 1.f); }

__device__ __forceinline__ uint32_t smem_u32(const void* p) {
    return (uint32_t)__cvta_generic_to_shared(p);
}
__device__ __forceinline__ void ldsm_x4(uint32_t* r, uint32_t addr) {
    asm volatile("ldmatrix.sync.aligned.m8n8.x4.shared.b16 {%0,%1,%2,%3}, [%4];"
                 : "=r"(r[0]), "=r"(r[1]), "=r"(r[2]), "=r"(r[3]) : "r"(addr));
}
__device__ __forceinline__ void ldsm_x4t(uint32_t* r, uint32_t addr) {
    asm volatile("ldmatrix.sync.aligned.m8n8.x4.trans.shared.b16 {%0,%1,%2,%3}, [%4];"
                 : "=r"(r[0]), "=r"(r[1]), "=r"(r[2]), "=r"(r[3]) : "r"(addr));
}
__device__ __forceinline__ void mma16816(float* d, const uint32_t* a, uint32_t b0, uint32_t b1) {
    asm volatile(
        "mma.sync.aligned.m16n8k16.row.col.f32.f16.f16.f32 "
        "{%0,%1,%2,%3}, {%4,%5,%6,%7}, {%8,%9}, {%0,%1,%2,%3};"
        : "+f"(d[0]), "+f"(d[1]), "+f"(d[2]), "+f"(d[3])
        : "r"(a[0]), "r"(a[1]), "r"(a[2]), "r"(a[3]), "r"(b0), "r"(b1));
}
__device__ __forceinline__ uint2 cvt_half4(float4 v) {
    __half2 lo = __floats2half2_rn(v.x, v.y);
    __half2 hi = __floats2half2_rn(v.z, v.w);
    uint2 r;
    r.x = *(uint32_t*)&lo;
    r.y = *(uint32_t*)&hi;
    return r;
}

// ---------------- x -> fp16 convert ------------------------------------------
__global__ void k_cvt(const float* __restrict__ x) {
    int i = blockIdx.x * blockDim.x + threadIdx.x;
    if (i < NN * IND / 4) {
        float4 v = ((const float4*)x)[i];
        ((uint2*)g_x1h)[i] = cvt_half4(v);
    }
}

// ---------------- bucketed CSR build -----------------------------------------
__global__ void k_initbkt() {
    int n = blockIdx.x * blockDim.x + threadIdx.x;
    if (n < NN) {
        g_cnt[n] = 1;
        g_csrc[(size_t)n * BKT] = n;    // self-loop
    }
}

__global__ void k_scatter_bkt(const int* __restrict__ ei) {
    int m4 = blockIdx.x * blockDim.x + threadIdx.x;
    if (m4 < EE / 4) {
        int4 s = ((const int4*)ei)[m4];
        int4 d = ((const int4*)(ei + EE))[m4];
        int i0 = atomicAdd(&g_cnt[d.x], 1);
        if (i0 < BKT) g_csrc[(size_t)d.x * BKT + i0] = s.x;
        int i1 = atomicAdd(&g_cnt[d.y], 1);
        if (i1 < BKT) g_csrc[(size_t)d.y * BKT + i1] = s.y;
        int i2 = atomicAdd(&g_cnt[d.z], 1);
        if (i2 < BKT) g_csrc[(size_t)d.z * BKT + i2] = s.z;
        int i3 = atomicAdd(&g_cnt[d.w], 1);
        if (i3 < BKT) g_csrc[(size_t)d.w * BKT + i3] = s.w;
    }
}

// ---------------- HMMA fp16 GEMM + fused attention-dot epilogue --------------
template <int L>
__global__ void __launch_bounds__(256) k_hgemm(
        const float* __restrict__ B,
        const float* __restrict__ att_s, const float* __restrict__ att_d) {
    constexpr int K   = (L == 1) ? IND : F1;
    constexpr int Nc  = (L == 1) ? F1  : HIDD;
    constexpr int H   = (L == 1) ? NH1 : 1;
    constexpr int NT  = K / 32;
    constexpr int NI  = Nc / 8;
    constexpr int LDA = 40;
    constexpr int LDB = Nc + 8;
    constexpr int APT = 4;
    constexpr int BPT = (32 * Nc / 4) / 256;
    const __half* A = (L == 1) ? (const __half*)g_x1h : (const __half*)g_x2;
    __half* C  = (L == 1) ? g_h1 : g_h2;
    float* as_ = (L == 1) ? g_as1 : g_as2;
    float* ad_ = (L == 1) ? g_ad1 : g_ad2;

    __shared__ __align__(16) __half As[2][128 * LDA];
    __shared__ __align__(16) __half Bs[2][32 * LDB];

    int tid = threadIdx.x;
    int w = tid >> 5, lane = tid & 31;
    int g = lane >> 2, t4 = lane & 3;
    int row0 = blockIdx.x * 128;

    uint2 pa[APT], pb[BPT];

    auto loadTile = [&](int t) {
        int k0 = t * 32;
        #pragma unroll
        for (int p = 0; p < APT; p++) {
            int idx = tid + p * 256;
            int r = idx >> 3, c4 = idx & 7;
            int gr = row0 + r;
            pa[p] = (gr < NN) ? *(const uint2*)&A[(size_t)gr * K + k0 + c4 * 4]
                              : make_uint2(0u, 0u);
        }
        #pragma unroll
        for (int p = 0; p < BPT; p++) {
            int idx = tid + p * 256;
            int r = idx / (Nc / 4), c4 = idx % (Nc / 4);
            pb[p] = cvt_half4(*(const float4*)&B[(size_t)(k0 + r) * Nc + c4 * 4]);
        }
    };
    auto stageTile = [&](int buf) {
        #pragma unroll
        for (int p = 0; p < APT; p++) {
            int idx = tid + p * 256;
            int r = idx >> 3, c4 = idx & 7;
            *(uint2*)&As[buf][r * LDA + c4 * 4] = pa[p];
        }
        #pragma unroll
        for (int p = 0; p < BPT; p++) {
            int idx = tid + p * 256;
            int r = idx / (Nc / 4), c4 = idx % (Nc / 4);
            *(uint2*)&Bs[buf][r * LDB + c4 * 4] = pb[p];
        }
    };

    float acc[NI][4];
    #pragma unroll
    for (int i = 0; i < NI; i++)
        #pragma unroll
        for (int j = 0; j < 4; j++) acc[i][j] = 0.f;

    loadTile(0);
    stageTile(0);
    __syncthreads();

    for (int t = 0; t < NT; t++) {
        if (t + 1 < NT) loadTile(t + 1);
        int buf = t & 1;
        #pragma unroll
        for (int ks = 0; ks < 2; ks++) {
            uint32_t a[4];
            ldsm_x4(a, smem_u32(&As[buf][(w * 16 + (lane & 15)) * LDA
                                         + ks * 16 + (lane >> 4) * 8]));
            #pragma unroll
            for (int nt = 0; nt < Nc / 16; nt++) {
                uint32_t b[4];
                ldsm_x4t(b, smem_u32(&Bs[buf][(ks * 16 + (lane & 15)) * LDB
                                              + nt * 16 + (lane >> 4) * 8]));
                mma16816(acc[2 * nt],     a, b[0], b[1]);
                mma16816(acc[2 * nt + 1], a, b[2], b[3]);
            }
        }
        if (t + 1 < NT) {
            stageTile((t + 1) & 1);
            __syncthreads();
        }
    }

    int r0 = row0 + w * 16 + g;
    #pragma unroll
    for (int ni = 0; ni < NI; ni++) {
        if (r0 < NN) {
            __half2 v = __floats2half2_rn(acc[ni][0], acc[ni][1]);
            *(__half2*)&C[(size_t)r0 * Nc + ni * 8 + t4 * 2] = v;
        }
        if (r0 + 8 < NN) {
            __half2 v = __floats2half2_rn(acc[ni][2], acc[ni][3]);
            *(__half2*)&C[(size_t)(r0 + 8) * Nc + ni * 8 + t4 * 2] = v;
        }
    }

    #pragma unroll
    for (int hh = 0; hh < H; hh++) {
        float s0 = 0.f, d0 = 0.f, s1 = 0.f, d1 = 0.f;
        #pragma unroll
        for (int ntl = 0; ntl < 8; ntl++) {
            int ni = hh * 8 + ntl;
            int lc = ntl * 8 + t4 * 2;
            float w0s = att_s[hh * 64 + lc],  w1s = att_s[hh * 64 + lc + 1];
            float w0d = att_d[hh * 64 + lc],  w1d = att_d[hh * 64 + lc + 1];
            s0 += acc[ni][0] * w0s + acc[ni][1] * w1s;
            d0 += acc[ni][0] * w0d + acc[ni][1] * w1d;
            s1 += acc[ni][2] * w0s + acc[ni][3] * w1s;
            d1 += acc[ni][2] * w0d + acc[ni][3] * w1d;
        }
        #pragma unroll
        for (int o = 1; o <= 2; o <<= 1) {
            s0 += __shfl_xor_sync(0xffffffffu, s0, o);
            d0 += __shfl_xor_sync(0xffffffffu, d0, o);
            s1 += __shfl_xor_sync(0xffffffffu, s1, o);
            d1 += __shfl_xor_sync(0xffffffffu, d1, o);
        }
        if (t4 == 0) {
            if (r0 < NN)     { as_[r0 * H + hh] = s0;       ad_[r0 * H + hh] = d0; }
            if (r0 + 8 < NN) { as_[(r0 + 8) * H + hh] = s1; ad_[(r0 + 8) * H + hh] = d1; }
        }
    }
}

// ---------------- fused softmax + aggregation + bias + ELU -------------------
// TWO warps per node, split along MESSAGES (alternating 32-message chunks).
// Both warps run the identical wide-load inner loop; partial feature
// accumulators + denominators combined once per node via smem.
// Grid is exactly NN/4 blocks of 8 warps (4 nodes x 2 warps).
template <int L>
__global__ void k_gather(const float* __restrict__ bias,
                         const float* __restrict__ Wl, const float* __restrict__ bl,
                         float* __restrict__ out) {
    constexpr int H = (L == 1) ? NH1 : 1;
    constexpr int F = H * HIDD;
    constexpr int VEC = F / 32;              // 4 (L1) or 2 (L2)
    const float* as_ = (L == 1) ? g_as1 : g_as2;
    const float* ad_ = (L == 1) ? g_ad1 : g_ad2;
    const __half* h  = (L == 1) ? (const __half*)g_h1 : (const __half*)g_h2;

    __shared__ float sacc[4][F];             // partner accumulator
    __shared__ float sd[4][2];               // partner denominators

    int wid = threadIdx.x >> 5;
    int gw = blockIdx.x * 8 + wid;
    int n = gw >> 1;
    int half = gw & 1;
    int slot = wid >> 1;
    int lane = threadIdx.x & 31;

    int beg = n * BKT;
    int cntn = min(g_cnt[n], BKT);
    int end = beg + cntn;

    float ad0 = ad_[n * H];
    float ad1 = (H == 2) ? ad_[n * H + 1] : 0.f;

    float acc[VEC];
    #pragma unroll
    for (int v = 0; v < VEC; v++) acc[v] = 0.f;
    float d0 = 0.f, d1 = 0.f;

    // ---- full 32-message chunks, alternating between the warp pair ----
    for (int c = beg + half * 32; c + 32 <= end; c += 64) {
        int src = g_csrc[c + lane];
        float ex0, ex1 = 0.f;
        if (H == 2) {
            float2 asv = *(const float2*)&as_[src * 2];
            ex0 = __expf(lrelu(asv.x + ad0));
            ex1 = __expf(lrelu(asv.y + ad1));
        } else {
            ex0 = __expf(lrelu(as_[src] + ad0));
        }
        d0 += ex0; d1 += ex1;
        #pragma unroll
        for (int j0 = 0; j0 < 32; j0 += 8) {
            uint2 raw2[8];
            uint32_t raw1[8];
            float wv[8];
            #pragma unroll
            for (int j = 0; j < 8; j++) {
                int s = __shfl_sync(0xffffffffu, src, j0 + j);
                float w0 = __shfl_sync(0xffffffffu, ex0, j0 + j);
                if (H == 2) {
                    float w1 = __shfl_sync(0xffffffffu, ex1, j0 + j);
                    wv[j] = (lane < 16) ? w0 : w1;
                } else {
                    wv[j] = w0;
                }
                if (VEC == 4) raw2[j] = *(const uint2*)(h + (size_t)s * F + lane * 4);
                else          raw1[j] = *(const uint32_t*)(h + (size_t)s * F + lane * 2);
            }
            #pragma unroll
            for (int j = 0; j < 8; j++) {
                if (VEC == 4) {
                    float2 f0 = __half22float2(*(__half2*)&raw2[j].x);
                    float2 f1 = __half22float2(*(__half2*)&raw2[j].y);
                    acc[0] += wv[j] * f0.x; acc[1] += wv[j] * f0.y;
                    acc[2] += wv[j] * f1.x; acc[3] += wv[j] * f1.y;
                } else {
                    float2 f0 = __half22float2(*(__half2*)&raw1[j]);
                    acc[0] += wv[j] * f0.x; acc[1] += wv[j] * f0.y;
                }
            }
        }
    }
    // ---- partial tail chunk: owned by the warp whose parity matches ----
    int tail = beg + (cntn & ~31);
    if ((cntn & 31) && (((tail - beg) >> 5) & 1) == half) {
        int m = tail + lane;
        int src = 0;
        float ex0 = 0.f, ex1 = 0.f;
        if (m < end) {
            src = g_csrc[m];
            ex0 = __expf(lrelu(as_[src * H] + ad0));
            if (H == 2) ex1 = __expf(lrelu(as_[src * H + 1] + ad1));
        }
        d0 += ex0; d1 += ex1;
        int cnt = end - tail;
        for (int j = 0; j < cnt; j++) {
            int s = __shfl_sync(0xffffffffu, src, j);
            float w0 = __shfl_sync(0xffffffffu, ex0, j);
            float w;
            if (H == 2) {
                float w1 = __shfl_sync(0xffffffffu, ex1, j);
                w = (lane < 16) ? w0 : w1;
            } else {
                w = w0;
            }
            if (VEC == 4) {
                uint2 raw = *(const uint2*)(h + (size_t)s * F + lane * 4);
                float2 f0 = __half22float2(*(__half2*)&raw.x);
                float2 f1 = __half22float2(*(__half2*)&raw.y);
                acc[0] += w * f0.x; acc[1] += w * f0.y;
                acc[2] += w * f1.x; acc[3] += w * f1.y;
            } else {
                float2 f0 = __half22float2(*(const __half2*)(h + (size_t)s * F + lane * 2));
                acc[0] += w * f0.x; acc[1] += w * f0.y;
            }
        }
    }

    // ---- warp-local denominator reduce ----
    #pragma unroll
    for (int o = 16; o; o >>= 1) {
        d0 += __shfl_xor_sync(0xffffffffu, d0, o);
        if (H == 2) d1 += __shfl_xor_sync(0xffffffffu, d1, o);
    }

    // ---- combine the warp pair via smem ----
    if (half == 1) {
        #pragma unroll
        for (int v = 0; v < VEC; v++) sacc[slot][lane * VEC + v] = acc[v];
        if (lane == 0) { sd[slot][0] = d0; sd[slot][1] = d1; }
    }
    __syncthreads();
    if (half == 1) return;

    #pragma unroll
    for (int v = 0; v < VEC; v++) acc[v] += sacc[slot][lane * VEC + v];
    d0 += sd[slot][0];
    d1 += sd[slot][1];

    float denom = (H == 2) ? ((lane < 16) ? d0 : d1) : d0;
    float inv = 1.f / denom;

    if (L == 1) {
        float o0 = eluf(acc[0] * inv + bias[lane * 4 + 0]);
        float o1 = eluf(acc[1] * inv + bias[lane * 4 + 1]);
        float o2 = eluf(acc[2] * inv + bias[lane * 4 + 2]);
        float o3 = eluf(acc[3] * inv + bias[lane * 4 + 3]);
        __half2 p0 = __floats2half2_rn(o0, o1);
        __half2 p1 = __floats2half2_rn(o2, o3);
        uint2 st;
        st.x = *(uint32_t*)&p0;
        st.y = *(uint32_t*)&p1;
        *(uint2*)((__half*)g_x2 + (size_t)n * F + lane * 4) = st;
    } else {
        float v0 = eluf(acc[0] * inv + bias[lane * 2 + 0]);
        float v1 = eluf(acc[1] * inv + bias[lane * 2 + 1]);
        int f0 = lane * 2, f1 = lane * 2 + 1;
        float cls[NCLS];
        #pragma unroll
        for (int j = 0; j < NCLS; j++)
            cls[j] = v0 * Wl[f0 * NCLS + j] + v1 * Wl[f1 * NCLS + j];
        #pragma unroll
        for (int o = 16; o; o >>= 1)
            #pragma unroll
            for (int j = 0; j < NCLS; j++)
                cls[j] += __shfl_xor_sync(0xffffffffu, cls[j], o);
        if (lane == 0) {
            #pragma unroll
            for (int j = 0; j < NCLS; j++)
                out[(size_t)n * NCLS + j] = cls[j] + bl[j];
        }
    }
}

// ---------------- launch ------------------------------------------------------
extern "C" void kernel_launch(void* const* d_in, const int* in_sizes, int n_in,
                              void* d_out, int out_size) {
    const float* x   = (const float*)d_in[0];
    const int*   ei  = (const int*)d_in[1];
    const float* W1  = (const float*)d_in[2];
    const float* as1 = (const float*)d_in[3];
    const float* ad1 = (const float*)d_in[4];
    const float* b1  = (const float*)d_in[5];
    const float* W2  = (const float*)d_in[6];
    const float* as2 = (const float*)d_in[7];
    const float* ad2 = (const float*)d_in[8];
    const float* b2  = (const float*)d_in[9];
    const float* Wl  = (const float*)d_in[10];
    const float* bl  = (const float*)d_in[11];
    float* out = (float*)d_out;

    static cudaStream_t s2 = nullptr;
    static cudaEvent_t e0 = nullptr, e1 = nullptr;
    if (!s2) {
        cudaStreamCreateWithFlags(&s2, cudaStreamNonBlocking);
        cudaEventCreateWithFlags(&e0, cudaEventDisableTiming);
        cudaEventCreateWithFlags(&e1, cudaEventDisableTiming);
    }

    const int T = 256;
    // ---- fork: bucketed CSR build on side stream ----
    cudaEventRecord(e0, 0);
    cudaStreamWaitEvent(s2, e0, 0);
    k_initbkt<<<(NN + T - 1) / T, T, 0, s2>>>();
    k_scatter_bkt<<<(EE / 4 + T - 1) / T, T, 0, s2>>>(ei);
    cudaEventRecord(e1, s2);

    // ---- main: convert x -> fp16, GEMM1 ----
    k_cvt<<<(NN * IND / 4 + T - 1) / T, T>>>(x);
    k_hgemm<1><<<(NN + 127) / 128, 256>>>(W1, as1, ad1);

    // ---- join, then the serial chain (2 warps per node => NN/4 blocks) ----
    cudaStreamWaitEvent(0, e1, 0);
    k_gather<1><<<NN / 4, 256>>>(b1, nullptr, nullptr, nullptr);
    k_hgemm<2><<<(NN + 127) / 128, 256>>>(W2, as2, ad2);
    k_gather<2><<<NN / 4, 256>>>(b2, Wl, bl, out);
}

// round 16
// speedup vs baseline: 1.2330x; 1.2330x over previous
#include <cuda_runtime.h>
#include <cuda_fp16.h>
#include <stdint.h>
#include <math.h>

#define NN   50000
#define EE   1600000
#define IND  256
#define HIDD 64
#define NH1  2
#define F1   128        // NH1*HIDD
#define NCLS 10
#define NEG  0.2f
#define BKT  96         // bucket capacity per node (mean deg 33, 11-sigma headroom)

// ---------------- scratch (static device globals; no allocation) ------------
__device__ __half g_h1[NN * F1];        // fp16 message features (layer 1)
__device__ __half g_h2[NN * HIDD];      // fp16 message features (layer 2)
__device__ float g_as1[NN * NH1], g_ad1[NN * NH1];
__device__ __half g_x2[NN * F1];        // fp16 input to GEMM2
__device__ float g_as2[NN], g_ad2[NN];

// bucketed CSR (built once per call; shared by both layers)
__device__ int g_cnt[NN];
__device__ int g_csrc[(size_t)NN * BKT];

// ---------------- helpers ----------------------------------------------------
__device__ __forceinline__ float lrelu(float x) { return x > 0.f ? x : NEG * x; }
__device__ __forceinline__ float eluf(float x)  { return x > 0.f ? x : (__expf(x) - 1.f); }

__device__ __forceinline__ uint32_t smem_u32(const void* p) {
    return (uint32_t)__cvta_generic_to_shared(p);
}
__device__ __forceinline__ void ldsm_x4(uint32_t* r, uint32_t addr) {
    asm volatile("ldmatrix.sync.aligned.m8n8.x4.shared.b16 {%0,%1,%2,%3}, [%4];"
                 : "=r"(r[0]), "=r"(r[1]), "=r"(r[2]), "=r"(r[3]) : "r"(addr));
}
__device__ __forceinline__ void ldsm_x4t(uint32_t* r, uint32_t addr) {
    asm volatile("ldmatrix.sync.aligned.m8n8.x4.trans.shared.b16 {%0,%1,%2,%3}, [%4];"
                 : "=r"(r[0]), "=r"(r[1]), "=r"(r[2]), "=r"(r[3]) : "r"(addr));
}
__device__ __forceinline__ void mma16816(float* d, const uint32_t* a, uint32_t b0, uint32_t b1) {
    asm volatile(
        "mma.sync.aligned.m16n8k16.row.col.f32.f16.f16.f32 "
        "{%0,%1,%2,%3}, {%4,%5,%6,%7}, {%8,%9}, {%0,%1,%2,%3};"
        : "+f"(d[0]), "+f"(d[1]), "+f"(d[2]), "+f"(d[3])
        : "r"(a[0]), "r"(a[1]), "r"(a[2]), "r"(a[3]), "r"(b0), "r"(b1));
}
__device__ __forceinline__ uint2 cvt_half4(float4 v) {
    __half2 lo = __floats2half2_rn(v.x, v.y);
    __half2 hi = __floats2half2_rn(v.z, v.w);
    uint2 r;
    r.x = *(uint32_t*)&lo;
    r.y = *(uint32_t*)&hi;
    return r;
}

// ---------------- bucketed CSR build -----------------------------------------
__global__ void k_initbkt() {
    int n = blockIdx.x * blockDim.x + threadIdx.x;
    if (n < NN) {
        g_cnt[n] = 1;
        g_csrc[(size_t)n * BKT] = n;    // self-loop
    }
}

__global__ void k_scatter_bkt(const int* __restrict__ ei) {
    int m4 = blockIdx.x * blockDim.x + threadIdx.x;
    if (m4 < EE / 4) {
        int4 s = ((const int4*)ei)[m4];
        int4 d = ((const int4*)(ei + EE))[m4];
        int i0 = atomicAdd(&g_cnt[d.x], 1);
        if (i0 < BKT) g_csrc[(size_t)d.x * BKT + i0] = s.x;
        int i1 = atomicAdd(&g_cnt[d.y], 1);
        if (i1 < BKT) g_csrc[(size_t)d.y * BKT + i1] = s.y;
        int i2 = atomicAdd(&g_cnt[d.z], 1);
        if (i2 < BKT) g_csrc[(size_t)d.z * BKT + i2] = s.z;
        int i3 = atomicAdd(&g_cnt[d.w], 1);
        if (i3 < BKT) g_csrc[(size_t)d.w * BKT + i3] = s.w;
    }
}

// ---------------- HMMA fp16 GEMM + fused attention-dot epilogue --------------
// L==1: A fp32 (input x), converted to fp16 during staging.
// L==2: A fp16 (g_x2), loaded directly.
template <int L>
__global__ void __launch_bounds__(256) k_hgemm(
        const float* __restrict__ Ain, const float* __restrict__ B,
        const float* __restrict__ att_s, const float* __restrict__ att_d) {
    constexpr int K   = (L == 1) ? IND : F1;
    constexpr int Nc  = (L == 1) ? F1  : HIDD;
    constexpr int H   = (L == 1) ? NH1 : 1;
    constexpr int NT  = K / 32;
    constexpr int NI  = Nc / 8;
    constexpr int LDA = 40;
    constexpr int LDB = Nc + 8;
    constexpr int APT = 4;
    constexpr int BPT = (32 * Nc / 4) / 256;
    const __half* Ah = (const __half*)g_x2;
    __half* C  = (L == 1) ? g_h1 : g_h2;
    float* as_ = (L == 1) ? g_as1 : g_as2;
    float* ad_ = (L == 1) ? g_ad1 : g_ad2;

    __shared__ __align__(16) __half As[2][128 * LDA];
    __shared__ __align__(16) __half Bs[2][32 * LDB];

    int tid = threadIdx.x;
    int w = tid >> 5, lane = tid & 31;
    int g = lane >> 2, t4 = lane & 3;
    int row0 = blockIdx.x * 128;

    uint2 pa[APT], pb[BPT];

    auto loadTile = [&](int t) {
        int k0 = t * 32;
        #pragma unroll
        for (int p = 0; p < APT; p++) {
            int idx = tid + p * 256;
            int r = idx >> 3, c4 = idx & 7;
            int gr = row0 + r;
            if (L == 1) {
                float4 v = (gr < NN) ? *(const float4*)&Ain[(size_t)gr * K + k0 + c4 * 4]
                                     : make_float4(0.f, 0.f, 0.f, 0.f);
                pa[p] = cvt_half4(v);
            } else {
                pa[p] = (gr < NN) ? *(const uint2*)&Ah[(size_t)gr * K + k0 + c4 * 4]
                                  : make_uint2(0u, 0u);
            }
        }
        #pragma unroll
        for (int p = 0; p < BPT; p++) {
            int idx = tid + p * 256;
            int r = idx / (Nc / 4), c4 = idx % (Nc / 4);
            pb[p] = cvt_half4(*(const float4*)&B[(size_t)(k0 + r) * Nc + c4 * 4]);
        }
    };
    auto stageTile = [&](int buf) {
        #pragma unroll
        for (int p = 0; p < APT; p++) {
            int idx = tid + p * 256;
            int r = idx >> 3, c4 = idx & 7;
            *(uint2*)&As[buf][r * LDA + c4 * 4] = pa[p];
        }
        #pragma unroll
        for (int p = 0; p < BPT; p++) {
            int idx = tid + p * 256;
            int r = idx / (Nc / 4), c4 = idx % (Nc / 4);
            *(uint2*)&Bs[buf][r * LDB + c4 * 4] = pb[p];
        }
    };

    float acc[NI][4];
    #pragma unroll
    for (int i = 0; i < NI; i++)
        #pragma unroll
        for (int j = 0; j < 4; j++) acc[i][j] = 0.f;

    loadTile(0);
    stageTile(0);
    __syncthreads();

    for (int t = 0; t < NT; t++) {
        if (t + 1 < NT) loadTile(t + 1);
        int buf = t & 1;
        #pragma unroll
        for (int ks = 0; ks < 2; ks++) {
            uint32_t a[4];
            ldsm_x4(a, smem_u32(&As[buf][(w * 16 + (lane & 15)) * LDA
                                         + ks * 16 + (lane >> 4) * 8]));
            #pragma unroll
            for (int nt = 0; nt < Nc / 16; nt++) {
                uint32_t b[4];
                ldsm_x4t(b, smem_u32(&Bs[buf][(ks * 16 + (lane & 15)) * LDB
                                              + nt * 16 + (lane >> 4) * 8]));
                mma16816(acc[2 * nt],     a, b[0], b[1]);
                mma16816(acc[2 * nt + 1], a, b[2], b[3]);
            }
        }
        if (t + 1 < NT) {
            stageTile((t + 1) & 1);
            __syncthreads();
        }
    }

    int r0 = row0 + w * 16 + g;
    #pragma unroll
    for (int ni = 0; ni < NI; ni++) {
        if (r0 < NN) {
            __half2 v = __floats2half2_rn(acc[ni][0], acc[ni][1]);
            *(__half2*)&C[(size_t)r0 * Nc + ni * 8 + t4 * 2] = v;
        }
        if (r0 + 8 < NN) {
            __half2 v = __floats2half2_rn(acc[ni][2], acc[ni][3]);
            *(__half2*)&C[(size_t)(r0 + 8) * Nc + ni * 8 + t4 * 2] = v;
        }
    }

    #pragma unroll
    for (int hh = 0; hh < H; hh++) {
        float s0 = 0.f, d0 = 0.f, s1 = 0.f, d1 = 0.f;
        #pragma unroll
        for (int ntl = 0; ntl < 8; ntl++) {
            int ni = hh * 8 + ntl;
            int lc = ntl * 8 + t4 * 2;
            float w0s = att_s[hh * 64 + lc],  w1s = att_s[hh * 64 + lc + 1];
            float w0d = att_d[hh * 64 + lc],  w1d = att_d[hh * 64 + lc + 1];
            s0 += acc[ni][0] * w0s + acc[ni][1] * w1s;
            d0 += acc[ni][0] * w0d + acc[ni][1] * w1d;
            s1 += acc[ni][2] * w0s + acc[ni][3] * w1s;
            d1 += acc[ni][2] * w0d + acc[ni][3] * w1d;
        }
        #pragma unroll
        for (int o = 1; o <= 2; o <<= 1) {
            s0 += __shfl_xor_sync(0xffffffffu, s0, o);
            d0 += __shfl_xor_sync(0xffffffffu, d0, o);
            s1 += __shfl_xor_sync(0xffffffffu, s1, o);
            d1 += __shfl_xor_sync(0xffffffffu, d1, o);
        }
        if (t4 == 0) {
            if (r0 < NN)     { as_[r0 * H + hh] = s0;       ad_[r0 * H + hh] = d0; }
            if (r0 + 8 < NN) { as_[(r0 + 8) * H + hh] = s1; ad_[(r0 + 8) * H + hh] = d1; }
        }
    }
}

// ---------------- fused softmax + aggregation + bias + ELU (warp per node) ---
// (R13 shape — best measured.) Full 32-message chunks: static 8-deep pipeline;
// <32 remainder: generic loop. L==1 writes fp16 x2; L==2 fuses classifier head.
template <int L>
__global__ void k_gather(const float* __restrict__ bias,
                         const float* __restrict__ Wl, const float* __restrict__ bl,
                         float* __restrict__ out) {
    constexpr int H = (L == 1) ? NH1 : 1;
    constexpr int F = H * HIDD;
    constexpr int VEC = F / 32;              // 4 (L1) or 2 (L2)
    const float* as_ = (L == 1) ? g_as1 : g_as2;
    const float* ad_ = (L == 1) ? g_ad1 : g_ad2;
    const __half* h  = (L == 1) ? (const __half*)g_h1 : (const __half*)g_h2;

    int n = (blockIdx.x * blockDim.x + threadIdx.x) >> 5;
    int lane = threadIdx.x & 31;
    if (n >= NN) return;

    int beg = n * BKT;
    int cntn = min(g_cnt[n], BKT);
    int end = beg + cntn;
    float ad0 = ad_[n * H];
    float ad1 = (H == 2) ? ad_[n * H + 1] : 0.f;

    float acc[VEC];
    #pragma unroll
    for (int v = 0; v < VEC; v++) acc[v] = 0.f;
    float d0 = 0.f, d1 = 0.f;

    int c = beg;
    for (; c + 32 <= end; c += 32) {
        int src = g_csrc[c + lane];
        float ex0, ex1 = 0.f;
        if (H == 2) {
            float2 asv = *(const float2*)&as_[src * 2];
            ex0 = __expf(lrelu(asv.x + ad0));
            ex1 = __expf(lrelu(asv.y + ad1));
        } else {
            ex0 = __expf(lrelu(as_[src] + ad0));
        }
        d0 += ex0; d1 += ex1;
        #pragma unroll
        for (int j0 = 0; j0 < 32; j0 += 8) {
            uint2 raw2[8];
            uint32_t raw1[8];
            float wv[8];
            #pragma unroll
            for (int j = 0; j < 8; j++) {
                int s = __shfl_sync(0xffffffffu, src, j0 + j);
                float w0 = __shfl_sync(0xffffffffu, ex0, j0 + j);
                if (H == 2) {
                    float w1 = __shfl_sync(0xffffffffu, ex1, j0 + j);
                    wv[j] = (lane < 16) ? w0 : w1;
                } else {
                    wv[j] = w0;
                }
                if (VEC == 4) raw2[j] = *(const uint2*)(h + (size_t)s * F + lane * 4);
                else          raw1[j] = *(const uint32_t*)(h + (size_t)s * F + lane * 2);
            }
            #pragma unroll
            for (int j = 0; j < 8; j++) {
                if (VEC == 4) {
                    float2 f0 = __half22float2(*(__half2*)&raw2[j].x);
                    float2 f1 = __half22float2(*(__half2*)&raw2[j].y);
                    acc[0] += wv[j] * f0.x; acc[1] += wv[j] * f0.y;
                    acc[2] += wv[j] * f1.x; acc[3] += wv[j] * f1.y;
                } else {
                    float2 f0 = __half22float2(*(__half2*)&raw1[j]);
                    acc[0] += wv[j] * f0.x; acc[1] += wv[j] * f0.y;
                }
            }
        }
    }
    if (c < end) {
        int m = c + lane;
        int src = 0;
        float ex0 = 0.f, ex1 = 0.f;
        if (m < end) {
            src = g_csrc[m];
            ex0 = __expf(lrelu(as_[src * H] + ad0));
            if (H == 2) ex1 = __expf(lrelu(as_[src * H + 1] + ad1));
        }
        d0 += ex0; d1 += ex1;
        int cnt = end - c;
        for (int j = 0; j < cnt; j++) {
            int s = __shfl_sync(0xffffffffu, src, j);
            float w0 = __shfl_sync(0xffffffffu, ex0, j);
            float w;
            if (H == 2) {
                float w1 = __shfl_sync(0xffffffffu, ex1, j);
                w = (lane < 16) ? w0 : w1;
            } else {
                w = w0;
            }
            if (VEC == 4) {
                uint2 raw = *(const uint2*)(h + (size_t)s * F + lane * 4);
                float2 f0 = __half22float2(*(__half2*)&raw.x);
                float2 f1 = __half22float2(*(__half2*)&raw.y);
                acc[0] += w * f0.x; acc[1] += w * f0.y;
                acc[2] += w * f1.x; acc[3] += w * f1.y;
            } else {
                float2 f0 = __half22float2(*(const __half2*)(h + (size_t)s * F + lane * 2));
                acc[0] += w * f0.x; acc[1] += w * f0.y;
            }
        }
    }

    #pragma unroll
    for (int o = 16; o; o >>= 1) {
        d0 += __shfl_xor_sync(0xffffffffu, d0, o);
        if (H == 2) d1 += __shfl_xor_sync(0xffffffffu, d1, o);
    }
    float denom = (H == 2) ? ((lane < 16) ? d0 : d1) : d0;
    float inv = 1.f / denom;

    if (L == 1) {
        float o0 = eluf(acc[0] * inv + bias[lane * 4 + 0]);
        float o1 = eluf(acc[1] * inv + bias[lane * 4 + 1]);
        float o2 = eluf(acc[2] * inv + bias[lane * 4 + 2]);
        float o3 = eluf(acc[3] * inv + bias[lane * 4 + 3]);
        __half2 p0 = __floats2half2_rn(o0, o1);
        __half2 p1 = __floats2half2_rn(o2, o3);
        uint2 st;
        st.x = *(uint32_t*)&p0;
        st.y = *(uint32_t*)&p1;
        *(uint2*)((__half*)g_x2 + (size_t)n * F + lane * 4) = st;
    } else {
        float v0 = eluf(acc[0] * inv + bias[lane * 2 + 0]);
        float v1 = eluf(acc[1] * inv + bias[lane * 2 + 1]);
        int f0 = lane * 2, f1 = lane * 2 + 1;
        float cls[NCLS];
        #pragma unroll
        for (int j = 0; j < NCLS; j++)
            cls[j] = v0 * Wl[f0 * NCLS + j] + v1 * Wl[f1 * NCLS + j];
        #pragma unroll
        for (int o = 16; o; o >>= 1)
            #pragma unroll
            for (int j = 0; j < NCLS; j++)
                cls[j] += __shfl_xor_sync(0xffffffffu, cls[j], o);
        if (lane == 0) {
            #pragma unroll
            for (int j = 0; j < NCLS; j++)
                out[(size_t)n * NCLS + j] = cls[j] + bl[j];
        }
    }
}

// ---------------- launch ------------------------------------------------------
extern "C" void kernel_launch(void* const* d_in, const int* in_sizes, int n_in,
                              void* d_out, int out_size) {
    const float* x   = (const float*)d_in[0];
    const int*   ei  = (const int*)d_in[1];
    const float* W1  = (const float*)d_in[2];
    const float* as1 = (const float*)d_in[3];
    const float* ad1 = (const float*)d_in[4];
    const float* b1  = (const float*)d_in[5];
    const float* W2  = (const float*)d_in[6];
    const float* as2 = (const float*)d_in[7];
    const float* ad2 = (const float*)d_in[8];
    const float* b2  = (const float*)d_in[9];
    const float* Wl  = (const float*)d_in[10];
    const float* bl  = (const float*)d_in[11];
    float* out = (float*)d_out;

    static cudaStream_t s2 = nullptr;
    static cudaEvent_t e0 = nullptr, e1 = nullptr;
    if (!s2) {
        cudaStreamCreateWithFlags(&s2, cudaStreamNonBlocking);
        cudaEventCreateWithFlags(&e0, cudaEventDisableTiming);
        cudaEventCreateWithFlags(&e1, cudaEventDisableTiming);
    }

    const int T = 256;
    // ---- fork: bucketed CSR build on side stream ----
    cudaEventRecord(e0, 0);
    cudaStreamWaitEvent(s2, e0, 0);
    k_initbkt<<<(NN + T - 1) / T, T, 0, s2>>>();
    k_scatter_bkt<<<(EE / 4 + T - 1) / T, T, 0, s2>>>(ei);
    cudaEventRecord(e1, s2);

    // ---- main: GEMM1 (fp32 A converted in staging) ----
    k_hgemm<1><<<(NN + 127) / 128, 256>>>(x, W1, as1, ad1);

    // ---- join, then the serial chain ----
    cudaStreamWaitEvent(0, e1, 0);
    k_gather<1><<<(NN + 7) / 8, 256>>>(b1, nullptr, nullptr, nullptr);
    k_hgemm<2><<<(NN + 127) / 128, 256>>>(nullptr, W2, as2, ad2);
    k_gather<2><<<(NN + 7) / 8, 256>>>(b2, Wl, bl, out);
}

// round 17
// speedup vs baseline: 1.3116x; 1.0637x over previous
#include <cuda_runtime.h>
#include <cuda_fp16.h>
#include <stdint.h>
#include <math.h>

#define NN   50000
#define EE   1600000
#define IND  256
#define HIDD 64
#define NH1  2
#define F1   128        // NH1*HIDD
#define NCLS 10
#define NEG  0.2f
#define BKT  96         // bucket capacity per node (mean deg 33, 11-sigma headroom)

// ---------------- scratch (static device globals; no allocation) ------------
__device__ __half g_h1[NN * F1];        // fp16 message features (layer 1)
__device__ __half g_h2[NN * HIDD];      // fp16 message features (layer 2)
__device__ float g_as1[NN * NH1], g_ad1[NN * NH1];
__device__ __half g_x2[NN * F1];        // fp16 input to GEMM2
__device__ float g_as2[NN], g_ad2[NN];

// bucketed CSR (built once per call; shared by both layers)
__device__ int g_cnt[NN];
__device__ int g_csrc[(size_t)NN * BKT];

// ---------------- helpers ----------------------------------------------------
__device__ __forceinline__ float lrelu(float x) { return x > 0.f ? x : NEG * x; }
__device__ __forceinline__ float eluf(float x)  { return x > 0.f ? x : (__expf(x) - 1.f); }

__device__ __forceinline__ uint32_t smem_u32(const void* p) {
    return (uint32_t)__cvta_generic_to_shared(p);
}
__device__ __forceinline__ void ldsm_x4(uint32_t* r, uint32_t addr) {
    asm volatile("ldmatrix.sync.aligned.m8n8.x4.shared.b16 {%0,%1,%2,%3}, [%4];"
                 : "=r"(r[0]), "=r"(r[1]), "=r"(r[2]), "=r"(r[3]) : "r"(addr));
}
__device__ __forceinline__ void ldsm_x4t(uint32_t* r, uint32_t addr) {
    asm volatile("ldmatrix.sync.aligned.m8n8.x4.trans.shared.b16 {%0,%1,%2,%3}, [%4];"
                 : "=r"(r[0]), "=r"(r[1]), "=r"(r[2]), "=r"(r[3]) : "r"(addr));
}
__device__ __forceinline__ void mma16816(float* d, const uint32_t* a, uint32_t b0, uint32_t b1) {
    asm volatile(
        "mma.sync.aligned.m16n8k16.row.col.f32.f16.f16.f32 "
        "{%0,%1,%2,%3}, {%4,%5,%6,%7}, {%8,%9}, {%0,%1,%2,%3};"
        : "+f"(d[0]), "+f"(d[1]), "+f"(d[2]), "+f"(d[3])
        : "r"(a[0]), "r"(a[1]), "r"(a[2]), "r"(a[3]), "r"(b0), "r"(b1));
}
__device__ __forceinline__ uint2 cvt_half4(float4 v) {
    __half2 lo = __floats2half2_rn(v.x, v.y);
    __half2 hi = __floats2half2_rn(v.z, v.w);
    uint2 r;
    r.x = *(uint32_t*)&lo;
    r.y = *(uint32_t*)&hi;
    return r;
}

// ---------------- bucketed CSR build -----------------------------------------
__global__ void k_initbkt() {
    int n = blockIdx.x * blockDim.x + threadIdx.x;
    if (n < NN) {
        g_cnt[n] = 1;
        g_csrc[(size_t)n * BKT] = n;    // self-loop
    }
}

__global__ void k_scatter_bkt(const int* __restrict__ ei) {
    int m4 = blockIdx.x * blockDim.x + threadIdx.x;
    if (m4 < EE / 4) {
        int4 s = ((const int4*)ei)[m4];
        int4 d = ((const int4*)(ei + EE))[m4];
        int i0 = atomicAdd(&g_cnt[d.x], 1);
        if (i0 < BKT) g_csrc[(size_t)d.x * BKT + i0] = s.x;
        int i1 = atomicAdd(&g_cnt[d.y], 1);
        if (i1 < BKT) g_csrc[(size_t)d.y * BKT + i1] = s.y;
        int i2 = atomicAdd(&g_cnt[d.z], 1);
        if (i2 < BKT) g_csrc[(size_t)d.z * BKT + i2] = s.z;
        int i3 = atomicAdd(&g_cnt[d.w], 1);
        if (i3 < BKT) g_csrc[(size_t)d.w * BKT + i3] = s.w;
    }
}

// ---------------- HMMA fp16 GEMM + fused attention-dot epilogue --------------
// L==1: A fp32 (input x), converted to fp16 during staging.
// L==2: A fp16 (g_x2), loaded directly.
// __launch_bounds__(256, 2): cap regs at 128 so 2 CTAs fit per SM.
template <int L>
__global__ void __launch_bounds__(256, 2) k_hgemm(
        const float* __restrict__ Ain, const float* __restrict__ B,
        const float* __restrict__ att_s, const float* __restrict__ att_d) {
    constexpr int K   = (L == 1) ? IND : F1;
    constexpr int Nc  = (L == 1) ? F1  : HIDD;
    constexpr int H   = (L == 1) ? NH1 : 1;
    constexpr int NT  = K / 32;
    constexpr int NI  = Nc / 8;
    constexpr int LDA = 40;
    constexpr int LDB = Nc + 8;
    constexpr int APT = 4;
    constexpr int BPT = (32 * Nc / 4) / 256;
    const __half* Ah = (const __half*)g_x2;
    __half* C  = (L == 1) ? g_h1 : g_h2;
    float* as_ = (L == 1) ? g_as1 : g_as2;
    float* ad_ = (L == 1) ? g_ad1 : g_ad2;

    __shared__ __align__(16) __half As[2][128 * LDA];
    __shared__ __align__(16) __half Bs[2][32 * LDB];

    int tid = threadIdx.x;
    int w = tid >> 5, lane = tid & 31;
    int g = lane >> 2, t4 = lane & 3;
    int row0 = blockIdx.x * 128;

    uint2 pa[APT], pb[BPT];

    auto loadTile = [&](int t) {
        int k0 = t * 32;
        #pragma unroll
        for (int p = 0; p < APT; p++) {
            int idx = tid + p * 256;
            int r = idx >> 3, c4 = idx & 7;
            int gr = row0 + r;
            if (L == 1) {
                float4 v = (gr < NN) ? *(const float4*)&Ain[(size_t)gr * K + k0 + c4 * 4]
                                     : make_float4(0.f, 0.f, 0.f, 0.f);
                pa[p] = cvt_half4(v);
            } else {
                pa[p] = (gr < NN) ? *(const uint2*)&Ah[(size_t)gr * K + k0 + c4 * 4]
                                  : make_uint2(0u, 0u);
            }
        }
        #pragma unroll
        for (int p = 0; p < BPT; p++) {
            int idx = tid + p * 256;
            int r = idx / (Nc / 4), c4 = idx % (Nc / 4);
            pb[p] = cvt_half4(*(const float4*)&B[(size_t)(k0 + r) * Nc + c4 * 4]);
        }
    };
    auto stageTile = [&](int buf) {
        #pragma unroll
        for (int p = 0; p < APT; p++) {
            int idx = tid + p * 256;
            int r = idx >> 3, c4 = idx & 7;
            *(uint2*)&As[buf][r * LDA + c4 * 4] = pa[p];
        }
        #pragma unroll
        for (int p = 0; p < BPT; p++) {
            int idx = tid + p * 256;
            int r = idx / (Nc / 4), c4 = idx % (Nc / 4);
            *(uint2*)&Bs[buf][r * LDB + c4 * 4] = pb[p];
        }
    };

    float acc[NI][4];
    #pragma unroll
    for (int i = 0; i < NI; i++)
        #pragma unroll
        for (int j = 0; j < 4; j++) acc[i][j] = 0.f;

    loadTile(0);
    stageTile(0);
    __syncthreads();

    for (int t = 0; t < NT; t++) {
        if (t + 1 < NT) loadTile(t + 1);
        int buf = t & 1;
        #pragma unroll
        for (int ks = 0; ks < 2; ks++) {
            uint32_t a[4];
            ldsm_x4(a, smem_u32(&As[buf][(w * 16 + (lane & 15)) * LDA
                                         + ks * 16 + (lane >> 4) * 8]));
            #pragma unroll
            for (int nt = 0; nt < Nc / 16; nt++) {
                uint32_t b[4];
                ldsm_x4t(b, smem_u32(&Bs[buf][(ks * 16 + (lane & 15)) * LDB
                                              + nt * 16 + (lane >> 4) * 8]));
                mma16816(acc[2 * nt],     a, b[0], b[1]);
                mma16816(acc[2 * nt + 1], a, b[2], b[3]);
            }
        }
        if (t + 1 < NT) {
            stageTile((t + 1) & 1);
            __syncthreads();
        }
    }

    int r0 = row0 + w * 16 + g;
    #pragma unroll
    for (int ni = 0; ni < NI; ni++) {
        if (r0 < NN) {
            __half2 v = __floats2half2_rn(acc[ni][0], acc[ni][1]);
            *(__half2*)&C[(size_t)r0 * Nc + ni * 8 + t4 * 2] = v;
        }
        if (r0 + 8 < NN) {
            __half2 v = __floats2half2_rn(acc[ni][2], acc[ni][3]);
            *(__half2*)&C[(size_t)(r0 + 8) * Nc + ni * 8 + t4 * 2] = v;
        }
    }

    #pragma unroll
    for (int hh = 0; hh < H; hh++) {
        float s0 = 0.f, d0 = 0.f, s1 = 0.f, d1 = 0.f;
        #pragma unroll
        for (int ntl = 0; ntl < 8; ntl++) {
            int ni = hh * 8 + ntl;
            int lc = ntl * 8 + t4 * 2;
            float w0s = att_s[hh * 64 + lc],  w1s = att_s[hh * 64 + lc + 1];
            float w0d = att_d[hh * 64 + lc],  w1d = att_d[hh * 64 + lc + 1];
            s0 += acc[ni][0] * w0s + acc[ni][1] * w1s;
            d0 += acc[ni][0] * w0d + acc[ni][1] * w1d;
            s1 += acc[ni][2] * w0s + acc[ni][3] * w1s;
            d1 += acc[ni][2] * w0d + acc[ni][3] * w1d;
        }
        #pragma unroll
        for (int o = 1; o <= 2; o <<= 1) {
            s0 += __shfl_xor_sync(0xffffffffu, s0, o);
            d0 += __shfl_xor_sync(0xffffffffu, d0, o);
            s1 += __shfl_xor_sync(0xffffffffu, s1, o);
            d1 += __shfl_xor_sync(0xffffffffu, d1, o);
        }
        if (t4 == 0) {
            if (r0 < NN)     { as_[r0 * H + hh] = s0;       ad_[r0 * H + hh] = d0; }
            if (r0 + 8 < NN) { as_[(r0 + 8) * H + hh] = s1; ad_[(r0 + 8) * H + hh] = d1; }
        }
    }
}

// ---------------- fused softmax + aggregation + bias + ELU (warp per node) ---
// Depth-4 load batching (fewer regs) + __launch_bounds__(256,5) for 62.5% occ.
// L==1 writes fp16 x2; L==2 fuses classifier head.
template <int L>
__global__ void __launch_bounds__(256, 5) k_gather(
        const float* __restrict__ bias,
        const float* __restrict__ Wl, const float* __restrict__ bl,
        float* __restrict__ out) {
    constexpr int H = (L == 1) ? NH1 : 1;
    constexpr int F = H * HIDD;
    constexpr int VEC = F / 32;              // 4 (L1) or 2 (L2)
    const float* as_ = (L == 1) ? g_as1 : g_as2;
    const float* ad_ = (L == 1) ? g_ad1 : g_ad2;
    const __half* h  = (L == 1) ? (const __half*)g_h1 : (const __half*)g_h2;

    int n = (blockIdx.x * blockDim.x + threadIdx.x) >> 5;
    int lane = threadIdx.x & 31;
    if (n >= NN) return;

    int beg = n * BKT;
    int cntn = min(g_cnt[n], BKT);
    int end = beg + cntn;
    float ad0 = ad_[n * H];
    float ad1 = (H == 2) ? ad_[n * H + 1] : 0.f;

    float acc[VEC];
    #pragma unroll
    for (int v = 0; v < VEC; v++) acc[v] = 0.f;
    float d0 = 0.f, d1 = 0.f;

    int c = beg;
    for (; c + 32 <= end; c += 32) {
        int src = g_csrc[c + lane];
        float ex0, ex1 = 0.f;
        if (H == 2) {
            float2 asv = *(const float2*)&as_[src * 2];
            ex0 = __expf(lrelu(asv.x + ad0));
            ex1 = __expf(lrelu(asv.y + ad1));
        } else {
            ex0 = __expf(lrelu(as_[src] + ad0));
        }
        d0 += ex0; d1 += ex1;
        #pragma unroll
        for (int j0 = 0; j0 < 32; j0 += 4) {
            uint2 raw2[4];
            uint32_t raw1[4];
            float wv[4];
            #pragma unroll
            for (int j = 0; j < 4; j++) {
                int s = __shfl_sync(0xffffffffu, src, j0 + j);
                float w0 = __shfl_sync(0xffffffffu, ex0, j0 + j);
                if (H == 2) {
                    float w1 = __shfl_sync(0xffffffffu, ex1, j0 + j);
                    wv[j] = (lane < 16) ? w0 : w1;
                } else {
                    wv[j] = w0;
                }
                if (VEC == 4) raw2[j] = *(const uint2*)(h + (size_t)s * F + lane * 4);
                else          raw1[j] = *(const uint32_t*)(h + (size_t)s * F + lane * 2);
            }
            #pragma unroll
            for (int j = 0; j < 4; j++) {
                if (VEC == 4) {
                    float2 f0 = __half22float2(*(__half2*)&raw2[j].x);
                    float2 f1 = __half22float2(*(__half2*)&raw2[j].y);
                    acc[0] += wv[j] * f0.x; acc[1] += wv[j] * f0.y;
                    acc[2] += wv[j] * f1.x; acc[3] += wv[j] * f1.y;
                } else {
                    float2 f0 = __half22float2(*(__half2*)&raw1[j]);
                    acc[0] += wv[j] * f0.x; acc[1] += wv[j] * f0.y;
                }
            }
        }
    }
    if (c < end) {
        int m = c + lane;
        int src = 0;
        float ex0 = 0.f, ex1 = 0.f;
        if (m < end) {
            src = g_csrc[m];
            ex0 = __expf(lrelu(as_[src * H] + ad0));
            if (H == 2) ex1 = __expf(lrelu(as_[src * H + 1] + ad1));
        }
        d0 += ex0; d1 += ex1;
        int cnt = end - c;
        for (int j = 0; j < cnt; j++) {
            int s = __shfl_sync(0xffffffffu, src, j);
            float w0 = __shfl_sync(0xffffffffu, ex0, j);
            float w;
            if (H == 2) {
                float w1 = __shfl_sync(0xffffffffu, ex1, j);
                w = (lane < 16) ? w0 : w1;
            } else {
                w = w0;
            }
            if (VEC == 4) {
                uint2 raw = *(const uint2*)(h + (size_t)s * F + lane * 4);
                float2 f0 = __half22float2(*(__half2*)&raw.x);
                float2 f1 = __half22float2(*(__half2*)&raw.y);
                acc[0] += w * f0.x; acc[1] += w * f0.y;
                acc[2] += w * f1.x; acc[3] += w * f1.y;
            } else {
                float2 f0 = __half22float2(*(const __half2*)(h + (size_t)s * F + lane * 2));
                acc[0] += w * f0.x; acc[1] += w * f0.y;
            }
        }
    }

    #pragma unroll
    for (int o = 16; o; o >>= 1) {
        d0 += __shfl_xor_sync(0xffffffffu, d0, o);
        if (H == 2) d1 += __shfl_xor_sync(0xffffffffu, d1, o);
    }
    float denom = (H == 2) ? ((lane < 16) ? d0 : d1) : d0;
    float inv = 1.f / denom;

    if (L == 1) {
        float o0 = eluf(acc[0] * inv + bias[lane * 4 + 0]);
        float o1 = eluf(acc[1] * inv + bias[lane * 4 + 1]);
        float o2 = eluf(acc[2] * inv + bias[lane * 4 + 2]);
        float o3 = eluf(acc[3] * inv + bias[lane * 4 + 3]);
        __half2 p0 = __floats2half2_rn(o0, o1);
        __half2 p1 = __floats2half2_rn(o2, o3);
        uint2 st;
        st.x = *(uint32_t*)&p0;
        st.y = *(uint32_t*)&p1;
        *(uint2*)((__half*)g_x2 + (size_t)n * F + lane * 4) = st;
    } else {
        float v0 = eluf(acc[0] * inv + bias[lane * 2 + 0]);
        float v1 = eluf(acc[1] * inv + bias[lane * 2 + 1]);
        int f0 = lane * 2, f1 = lane * 2 + 1;
        float cls[NCLS];
        #pragma unroll
        for (int j = 0; j < NCLS; j++)
            cls[j] = v0 * Wl[f0 * NCLS + j] + v1 * Wl[f1 * NCLS + j];
        #pragma unroll
        for (int o = 16; o; o >>= 1)
            #pragma unroll
            for (int j = 0; j < NCLS; j++)
                cls[j] += __shfl_xor_sync(0xffffffffu, cls[j], o);
        if (lane == 0) {
            #pragma unroll
            for (int j = 0; j < NCLS; j++)
                out[(size_t)n * NCLS + j] = cls[j] + bl[j];
        }
    }
}

// ---------------- launch ------------------------------------------------------
extern "C" void kernel_launch(void* const* d_in, const int* in_sizes, int n_in,
                              void* d_out, int out_size) {
    const float* x   = (const float*)d_in[0];
    const int*   ei  = (const int*)d_in[1];
    const float* W1  = (const float*)d_in[2];
    const float* as1 = (const float*)d_in[3];
    const float* ad1 = (const float*)d_in[4];
    const float* b1  = (const float*)d_in[5];
    const float* W2  = (const float*)d_in[6];
    const float* as2 = (const float*)d_in[7];
    const float* ad2 = (const float*)d_in[8];
    const float* b2  = (const float*)d_in[9];
    const float* Wl  = (const float*)d_in[10];
    const float* bl  = (const float*)d_in[11];
    float* out = (float*)d_out;

    static cudaStream_t s2 = nullptr;
    static cudaEvent_t e0 = nullptr, e1 = nullptr;
    if (!s2) {
        cudaStreamCreateWithFlags(&s2, cudaStreamNonBlocking);
        cudaEventCreateWithFlags(&e0, cudaEventDisableTiming);
        cudaEventCreateWithFlags(&e1, cudaEventDisableTiming);
    }

    const int T = 256;
    // ---- fork: bucketed CSR build on side stream ----
    cudaEventRecord(e0, 0);
    cudaStreamWaitEvent(s2, e0, 0);
    k_initbkt<<<(NN + T - 1) / T, T, 0, s2>>>();
    k_scatter_bkt<<<(EE / 4 + T - 1) / T, T, 0, s2>>>(ei);
    cudaEventRecord(e1, s2);

    // ---- main: GEMM1 (fp32 A converted in staging) ----
    k_hgemm<1><<<(NN + 127) / 128, 256>>>(x, W1, as1, ad1);

    // ---- join, then the serial chain ----
    cudaStreamWaitEvent(0, e1, 0);
    k_gather<1><<<(NN + 7) / 8, 256>>>(b1, nullptr, nullptr, nullptr);
    k_hgemm<2><<<(NN + 127) / 128, 256>>>(nullptr, W2, as2, ad2);
    k_gather<2><<<(NN + 7) / 8, 256>>>(b2, Wl, bl, out);
}